// round 8
// baseline (speedup 1.0000x reference)
#include <cuda_runtime.h>

#define NB   16
#define CTA_THREADS 256      // 8 warps = 4 warp-pairs per CTA
#define NCTA 256             // 16 batches * 64 branches * 2 warps / 8 warps per CTA

__device__ float g_part[NCTA*8];
__device__ unsigned int g_ticket;

__device__ __forceinline__ float2 cmul(float2 a, float2 b){
    return make_float2(fmaf(a.x, b.x, -a.y*b.y), fmaf(a.x, b.y, a.y*b.x));
}
__device__ __forceinline__ float2 cadd(float2 a, float2 b){
    return make_float2(a.x + b.x, a.y + b.y);
}
__device__ __forceinline__ float2 shflx(float2 v, int m){
    float2 r;
    r.x = __shfl_xor_sync(0xffffffffu, v.x, m);
    r.y = __shfl_xor_sync(0xffffffffu, v.y, m);
    return r;
}
__device__ __forceinline__ void barpair(int id){
    asm volatile("bar.sync %0, %1;" :: "r"(id), "r"(64) : "memory");
}

// ---------------- gates on 4-amp state (local bits = q0,q1) ----------------------
__device__ __forceinline__ void sq_local(float2* a, int q,
        float2 u00, float2 u01, float2 u10, float2 u11){
    int m = 1 << q;
    #pragma unroll
    for (int i = 0; i < 4; i++){
        if (!(i & m)){
            int j = i | m;
            float2 x = a[i], y = a[j];
            a[i] = cadd(cmul(u00, x), cmul(u01, y));
            a[j] = cadd(cmul(u10, x), cmul(u11, y));
        }
    }
}
__device__ __forceinline__ void sq_lane(float2* a, int lane, int lb,
        float2 u00, float2 u01, float2 u10, float2 u11){
    int m = 1 << lb;
    bool hi = (lane >> lb) & 1;
    float2 cs = hi ? u11 : u00;
    float2 cx = hi ? u10 : u01;
    #pragma unroll
    for (int i = 0; i < 4; i++){
        float2 p = shflx(a[i], m);
        a[i] = cadd(cmul(cs, a[i]), cmul(cx, p));
    }
}
// pair on local bits 0,1: {00,11} via pA/pB, {01,10} via qC/qD
__device__ __forceinline__ void pair_LL01(float2* a,
        float2 pA, float2 pB, float2 qC, float2 qD){
    float2 a0=a[0], a1=a[1], a2=a[2], a3=a[3];
    a[0] = cadd(cmul(pA,a0), cmul(pB,a3));
    a[3] = cadd(cmul(pB,a0), cmul(pA,a3));
    a[1] = cadd(cmul(qC,a1), cmul(qD,a2));
    a[2] = cadd(cmul(qD,a1), cmul(qC,a2));
}
__device__ __forceinline__ void pair_NN(float2* a, int lane, int LA, int LB,
        float2 pA, float2 pB, float2 qC, float2 qD){
    int M = (1<<LA) | (1<<LB);
    bool eq = ((((lane >> LA) ^ (lane >> LB)) & 1) == 0);
    float2 X = eq ? pA : qC;
    float2 Y = eq ? pB : qD;
    #pragma unroll
    for (int i = 0; i < 4; i++){
        float2 p = shflx(a[i], M);
        a[i] = cadd(cmul(X, a[i]), cmul(Y, p));
    }
}
// pair: local bit1 (q1) + lane bit LB
__device__ __forceinline__ void pair_ML(float2* a, int lane, int LB,
        float2 pA, float2 pB, float2 qC, float2 qD){
    int lm = 1 << LB;
    int b4 = (lane >> LB) & 1;
    float2 Xi = b4 ? qC : pA, Yi = b4 ? qD : pB;
    float2 Xj = b4 ? pA : qC, Yj = b4 ? pB : qD;
    #pragma unroll
    for (int i = 0; i < 2; i++){
        int j = i | 2;
        float2 pj = shflx(a[j], lm);
        float2 pi = shflx(a[i], lm);
        a[i] = cadd(cmul(Xi, a[i]), cmul(Yi, pj));
        a[j] = cadd(cmul(Xj, a[j]), cmul(Yj, pi));
    }
}

// ---------------- setup builders (verified rounds 1-7) ---------------------------
__device__ void build_ufinal4(const float* vw, float2* F){
    float s1, c1, s2, c2, sz, cz;
    __sincosf(0.5f*vw[0], &s1, &c1);
    __sincosf(0.5f*vw[1], &s2, &c2);
    __sincosf(0.5f*vw[2], &sz, &cz);
    float2 m00 = make_float2( c1*c2,  s1*s2);
    float2 m01 = make_float2(-c1*s2, -c2*s1);
    float2 m10 = make_float2( c1*s2, -c2*s1);
    float2 m11 = make_float2( c1*c2, -s1*s2);
    float2 e0 = make_float2(cz, -sz);
    float2 e1 = make_float2(cz,  sz);
    F[0] = cmul(e0, m00); F[1] = cmul(e0, m01);
    F[2] = cmul(e1, m10); F[3] = cmul(e1, m11);
}
__device__ void lcompose_rx(float2* F, float c, float s){     // F <- Rx * F
    float2 is = make_float2(0.f, -s);
    float2 n0 = cadd(make_float2(c*F[0].x, c*F[0].y), cmul(is, F[2]));
    float2 n1 = cadd(make_float2(c*F[1].x, c*F[1].y), cmul(is, F[3]));
    float2 n2 = cadd(cmul(is, F[0]), make_float2(c*F[2].x, c*F[2].y));
    float2 n3 = cadd(cmul(is, F[1]), make_float2(c*F[3].x, c*F[3].y));
    F[0]=n0; F[1]=n1; F[2]=n2; F[3]=n3;
}
__device__ void lcompose_ry(float2* F, float c, float s){     // F <- Ry * F
    float2 n0 = make_float2(fmaf(c,F[0].x,-s*F[2].x), fmaf(c,F[0].y,-s*F[2].y));
    float2 n1 = make_float2(fmaf(c,F[1].x,-s*F[3].x), fmaf(c,F[1].y,-s*F[3].y));
    float2 n2 = make_float2(fmaf(s,F[0].x, c*F[2].x), fmaf(s,F[0].y, c*F[2].y));
    float2 n3 = make_float2(fmaf(s,F[1].x, c*F[3].x), fmaf(s,F[1].y, c*F[3].y));
    F[0]=n0; F[1]=n1; F[2]=n2; F[3]=n3;
}
__device__ void paircoef(const float* w, int layer, int pidx, float2* co){
    const float* wl = w + layer*48 + 3*pidx;
    float ca, sa, cb, sb, cg, sg;
    __sincosf(0.5f*wl[0], &sa, &ca);
    __sincosf(0.5f*wl[1], &sb, &cb);
    __sincosf(0.5f*wl[2], &sg, &cg);
    float A  = ca*cb + sa*sb;
    float Bi = ca*sb - cb*sa;
    float C  = ca*cb - sa*sb;
    float Di = -(sa*cb + ca*sb);
    float2 p  = make_float2(cg, -sg);
    float2 qf = make_float2(cg,  sg);
    co[0] = make_float2(p.x*A, p.y*A);
    co[1] = cmul(p,  make_float2(0.f, Bi));
    co[2] = make_float2(qf.x*C, qf.y*C);
    co[3] = cmul(qf, make_float2(0.f, Di));
}

__global__ void __launch_bounds__(CTA_THREADS, 2)
qpie_split(const float* __restrict__ x,
           const float* __restrict__ w,
           const float* __restrict__ pw,
           float* __restrict__ out)
{
    const float c8 = 0.9238795325112867f;
    const float s8 = 0.3826834323650898f;

    __shared__ float2 sT[16];          // L0 record per-qubit e^{i pw/2}
    __shared__ float2 sXcs[8];         // (cos,sin) of x_q/2
    __shared__ float2 sOL[64];         // odd-record lane tables (q2..q6), rec 2,3
    __shared__ float2 sOLoc[8];        // odd-record local tables (q0,q1), 4 each
    __shared__ float2 sOq7[2];         // odd-record q7 factor
    __shared__ float2 sPair[84];       // 21 pairs x 4 coefs
    __shared__ float2 sF01[32];        // Rx(x)*U0 per qubit (8 x 4)
    __shared__ float2 sF2[32];         // U2 per qubit
    __shared__ float2 sF12[128];       // D(v4,v5)*Ry(x)*U1: 8 qubits x 4 variants x 4
    __shared__ float2 sExch[2048];     // exchange: [buf][pair][sub][lane][amp]
    __shared__ float  sRed[64];
    __shared__ int    sLast;

    int tid  = threadIdx.x;
    int lane = tid & 31;
    int wid  = tid >> 5;
    int sub  = wid & 1;                // q7 value for this warp
    int pairIdx = wid >> 1;            // warp-pair within CTA (0..3)
    int cta  = blockIdx.x;
    int b    = cta >> 4;               // 16 CTAs per batch
    int br   = (cta & 15)*4 + pairIdx; // branch 0..63
    const float* xb = x + b*8;

    // ================= cooperative setup (167 jobs, one round) =============
    {
        int job = tid;
        if (job < 16){
            int r = job >> 3, q = job & 7;
            float s, c; __sincosf(0.5f*pw[r*8 + q], &s, &c);
            sT[r*8 + q] = make_float2(c, s);
        } else if (job < 24){
            int q = job - 16;
            float s, c; __sincosf(0.5f*xb[q], &s, &c);
            sXcs[q] = make_float2(c, s);
        } else if (job < 88){        // odd-record lane tables over q2..q6
            int k = job - 24; int r = k >> 5; int ln = k & 31;
            const float* pwa = pw + (2 + r)*8;
            float sum = 0.f;
            #pragma unroll
            for (int j = 0; j < 5; j++)
                if ((ln >> j) & 1) sum += pwa[2+j];
            float sp, cp; __sincosf(0.5f*sum, &sp, &cp);
            sOL[k] = make_float2(cp, sp);
        } else if (job < 96){        // odd-record local tables over q0,q1
            int k = job - 88; int r = k >> 2; int i = k & 3;
            const float* pwa = pw + (2 + r)*8;
            float sum = 0.f;
            if (i & 1) sum += pwa[0];
            if (i & 2) sum += pwa[1];
            float sp, cp; __sincosf(0.5f*sum, &sp, &cp);
            sOLoc[k] = make_float2(cp, sp);
        } else if (job < 98){        // odd-record q7 factors
            int r = job - 96;
            float sp, cp; __sincosf(0.5f*pw[(2 + r)*8 + 7], &sp, &cp);
            sOq7[r] = make_float2(cp, sp);
        } else if (job < 119){       // pair coefficients (7 per layer)
            int k = job - 98; int layer = k/7, p = k - layer*7;
            paircoef(w, layer, p, sPair + k*4);
        } else if (job < 127){       // F01 = Rx(x)*U0 per qubit
            int q = job - 119;
            float2 F[4];
            build_ufinal4(w + 24 + 3*q, F);
            float s, c; __sincosf(0.5f*xb[q], &s, &c);
            lcompose_rx(F, c, s);
            sF01[q*4+0]=F[0]; sF01[q*4+1]=F[1]; sF01[q*4+2]=F[2]; sF01[q*4+3]=F[3];
        } else if (job < 135){       // F2 = U2 per qubit
            int q = job - 127;
            float2 F[4];
            build_ufinal4(w + 96 + 24 + 3*q, F);
            sF2[q*4+0]=F[0]; sF2[q*4+1]=F[1]; sF2[q*4+2]=F[2]; sF2[q*4+3]=F[3];
        } else if (job < 167){       // F12 variants = D(v4,v5)*Ry(x)*U1
            int k = job - 135; int q = k >> 2, vv = k & 3;
            float2 F[4];
            build_ufinal4(w + 48 + 24 + 3*q, F);
            float s, c; __sincosf(0.5f*xb[q], &s, &c);
            lcompose_ry(F, c, s);
            float s4 = (vv & 1) ? 1.f : -1.f;
            float s5 = (vv & 2) ? 1.f : -1.f;
            float th = 0.5f*(s4*pw[32 + q] + s5*pw[40 + q]);
            float sp, cp; __sincosf(th, &sp, &cp);
            float2 d = make_float2(cp, sp);
            F[2] = cmul(d, F[2]); F[3] = cmul(d, F[3]);
            float2* dst = sF12 + (q*4 + vv)*4;
            dst[0]=F[0]; dst[1]=F[1]; dst[2]=F[2]; dst[3]=F[3];
        }
    }
    __syncthreads();

    // ================= product-state init (H + Ry(x) + L0 records) =========
    // K = 1/16 (H^8) * 1/2 (L0 records) * 1/2 (L2 records) = 0.015625
    float2 a[4];
    {
        float sg0 = (br & 1) ? 1.f : -1.f;
        float sg1 = (br & 2) ? 1.f : -1.f;
        float2 g0[8], g1[8];
        #pragma unroll
        for (int q = 0; q < 8; q++){
            float2 t0 = sT[q], t1 = sT[8+q];
            float2 E = cmul(make_float2(t0.x, sg0*t0.y),
                            make_float2(t1.x, sg1*t1.y));
            float2 cs = sXcs[q];
            float gm = cs.x - cs.y, gp = cs.x + cs.y;
            g0[q] = make_float2(gm, 0.f);
            g1[q] = make_float2(gp*E.x, gp*E.y);
        }
        float2 lp = make_float2(0.015625f, 0.f);
        #pragma unroll
        for (int j = 0; j < 5; j++)
            lp = cmul(lp, ((lane >> j) & 1) ? g1[2+j] : g0[2+j]);
        lp = cmul(lp, sub ? g1[7] : g0[7]);
        a[0] = cmul(lp, cmul(g0[0], g0[1]));
        a[1] = cmul(lp, cmul(g1[0], g0[1]));
        a[2] = cmul(lp, cmul(g0[0], g1[1]));
        a[3] = cmul(lp, cmul(g1[0], g1[1]));
    }

    int vv = (br >> 4) & 3;
    int bufp = 0;
    int myBase   = ((pairIdx*2 + sub)*32 + lane)*4;
    int pBaseSq  = ((pairIdx*2 + (sub^1))*32 + lane)*4;        // same lane, other warp
    int pBaseMP  = ((pairIdx*2 + (sub^1))*32 + (lane^16))*4;   // lane bit4 flip too
    int barId = 1 + pairIdx;

    #pragma unroll
    for (int layer = 0; layer < 3; layer++){
        // ---- L1 merged odd-record diagonal (records 2,3) ----
        if (layer == 1){
            int v2 = (br >> 2) & 1, v3 = (br >> 3) & 1;
            float2 eL2 = cmul(sOL[lane],      sub ? sOq7[0] : make_float2(1.f,0.f));
            float2 eL3 = cmul(sOL[32 + lane], sub ? sOq7[1] : make_float2(1.f,0.f));
            int par = v2 ^ v3;
            float sgn = v2 ? -1.f : 1.f;
            #pragma unroll
            for (int i = 0; i < 4; i++){
                float2 e2 = cmul(eL2, sOLoc[i]);
                float2 e3 = cmul(eL3, sOLoc[4+i]);
                float m = (v2 ? e2.y : e2.x) * (v3 ? e3.y : e3.x);
                if (par) a[i] = make_float2(a[i].y*m, -a[i].x*m);   // * (-i m)
                else { float mm = sgn*m; a[i] = make_float2(a[i].x*mm, a[i].y*mm); }
            }
        }

        const float2* P = sPair + layer*28;

        // p0 (q0,q1) + CCRX(rec, q0 -> q1)
        pair_LL01(a, P[0], P[1], P[2], P[3]);
        if ((br >> (2*layer)) & 1){
            float2 ai = a[1], aj = a[3];
            a[1] = make_float2(fmaf(c8, ai.x,  s8*aj.y), fmaf(c8, ai.y, -s8*aj.x));
            a[3] = make_float2(fmaf(c8, aj.x,  s8*ai.y), fmaf(c8, aj.y, -s8*ai.x));
        }
        // p1 (q2,q3) + CCRX(rec, q2 -> q3)
        pair_NN(a, lane, 0, 1, P[4], P[5], P[6], P[7]);
        if ((br >> (2*layer + 1)) & 1){
            bool act = lane & 1;
            #pragma unroll
            for (int i = 0; i < 4; i++){
                float2 p = shflx(a[i], 2);
                if (act)
                    a[i] = make_float2(fmaf(c8, a[i].x,  s8*p.y), fmaf(c8, a[i].y, -s8*p.x));
            }
        }
        // p2 (q4,q5)
        pair_NN(a, lane, 2, 3, P[8], P[9], P[10], P[11]);
        // p3 (q6,q7): smem exchange pass
        {
            bool eq = (((lane >> 4) & 1) == sub);
            float2 X = eq ? P[12] : P[14];
            float2 Y = eq ? P[13] : P[15];
            float2* mb = sExch + bufp*1024 + myBase;
            mb[0]=a[0]; mb[1]=a[1]; mb[2]=a[2]; mb[3]=a[3];
            barpair(barId);
            const float2* pb = sExch + bufp*1024 + pBaseMP;
            #pragma unroll
            for (int i = 0; i < 4; i++)
                a[i] = cadd(cmul(X, a[i]), cmul(Y, pb[i]));
            bufp ^= 1;
        }
        // offset pairs (q1,q2), (q3,q4), (q5,q6)
        pair_ML(a, lane, 0,    P[16], P[17], P[18], P[19]);
        pair_NN(a, lane, 1, 2, P[20], P[21], P[22], P[23]);
        pair_NN(a, lane, 3, 4, P[24], P[25], P[26], P[27]);

        // ---- fused single-qubit gates ----
        const float2* FT = (layer == 0) ? sF01 : (layer == 2) ? sF2 : nullptr;
        #pragma unroll
        for (int q = 0; q < 8; q++){
            const float2* F = (layer == 1) ? (sF12 + (q*4 + vv)*4) : (FT + q*4);
            float2 u00 = F[0], u01 = F[1], u10 = F[2], u11 = F[3];
            if (q < 2){
                sq_local(a, q, u00, u01, u10, u11);
            } else if (q < 7){
                sq_lane(a, lane, q-2, u00, u01, u10, u11);
            } else {
                // q7: smem exchange
                float2 us = sub ? u11 : u00;
                float2 ux = sub ? u10 : u01;
                float2* mb = sExch + bufp*1024 + myBase;
                mb[0]=a[0]; mb[1]=a[1]; mb[2]=a[2]; mb[3]=a[3];
                barpair(barId);
                const float2* pb = sExch + bufp*1024 + pBaseSq;
                #pragma unroll
                for (int i = 0; i < 4; i++)
                    a[i] = cadd(cmul(us, a[i]), cmul(ux, pb[i]));
                bufp ^= 1;
            }
        }
    }

    // ================= measurement & fused reduction =======================
    float e[8];
    float tot = 0.f;
    e[0] = 0.f; e[1] = 0.f;
    #pragma unroll
    for (int i = 0; i < 4; i++){
        float p = fmaf(a[i].x, a[i].x, a[i].y*a[i].y);
        tot += p;
        e[0] += (i & 1) ? -p : p;
        e[1] += (i & 2) ? -p : p;
    }
    #pragma unroll
    for (int q = 0; q < 5; q++)
        e[2+q] = ((lane >> q) & 1) ? -tot : tot;
    e[7] = sub ? -tot : tot;

    #pragma unroll
    for (int q = 0; q < 8; q++){
        #pragma unroll
        for (int s = 16; s; s >>= 1)
            e[q] += __shfl_xor_sync(0xffffffffu, e[q], s);
    }
    if (lane == 0){
        #pragma unroll
        for (int q = 0; q < 8; q++) sRed[wid*8 + q] = e[q];
    }
    __syncthreads();

    if (tid < 8){
        float s = 0.f;
        #pragma unroll
        for (int wq = 0; wq < 8; wq++) s += sRed[wq*8 + tid];
        g_part[cta*8 + tid] = s;
        __threadfence();
    }
    __syncthreads();

    if (tid == 0){
        __threadfence();
        unsigned int t = atomicAdd(&g_ticket, 1u);
        sLast = (t == NCTA - 1) ? 1 : 0;
    }
    __syncthreads();

    if (sLast){
        __threadfence();
        if (tid < 128){
            int bb = tid >> 3, q = tid & 7;
            float s = 0.f;
            #pragma unroll
            for (int k = 0; k < 16; k++)
                s += g_part[(bb*16 + k)*8 + q];
            out[tid] = s;
        }
        __syncthreads();
        if (tid == 0) g_ticket = 0;
    }
}

extern "C" void kernel_launch(void* const* d_in, const int* in_sizes, int n_in,
                              void* d_out, int out_size){
    const float* x  = (const float*)d_in[0];   // (16, 8)
    const float* w  = (const float*)d_in[1];   // (3, 48)
    const float* pw = (const float*)d_in[2];   // (3, 2, 8)
    float* out = (float*)d_out;                // (16, 8)

    qpie_split<<<NCTA, CTA_THREADS>>>(x, w, pw, out);
}

// round 9
// speedup vs baseline: 1.1597x; 1.1597x over previous
#include <cuda_runtime.h>

#define NB   16
#define CTA_THREADS 512      // 16 warps = 8 warp-pairs
#define NCTA 128             // 16 batches * 8 (branch bits 0-2) -> 1 CTA/SM

__device__ float g_part[NCTA*8];
__device__ unsigned int g_ticket;

__device__ __forceinline__ float2 cmul(float2 a, float2 b){
    return make_float2(fmaf(a.x, b.x, -a.y*b.y), fmaf(a.x, b.y, a.y*b.x));
}
__device__ __forceinline__ float2 cadd(float2 a, float2 b){
    return make_float2(a.x + b.x, a.y + b.y);
}
__device__ __forceinline__ float2 shflx(float2 v, int m){
    float2 r;
    r.x = __shfl_xor_sync(0xffffffffu, v.x, m);
    r.y = __shfl_xor_sync(0xffffffffu, v.y, m);
    return r;
}
__device__ __forceinline__ void barpair(int id){
    asm volatile("bar.sync %0, %1;" :: "r"(id), "r"(64) : "memory");
}

// ---------------- gates on 4-amp state (local bits = q0,q1; lane bits = q2..q6) --
__device__ __forceinline__ void sq_local(float2* a, int q,
        float2 u00, float2 u01, float2 u10, float2 u11){
    int m = 1 << q;
    #pragma unroll
    for (int i = 0; i < 4; i++){
        if (!(i & m)){
            int j = i | m;
            float2 x = a[i], y = a[j];
            a[i] = cadd(cmul(u00, x), cmul(u01, y));
            a[j] = cadd(cmul(u10, x), cmul(u11, y));
        }
    }
}
__device__ __forceinline__ void sq_lane(float2* a, int lane, int lb,
        float2 u00, float2 u01, float2 u10, float2 u11){
    int m = 1 << lb;
    bool hi = (lane >> lb) & 1;
    float2 cs = hi ? u11 : u00;
    float2 cx = hi ? u10 : u01;
    #pragma unroll
    for (int i = 0; i < 4; i++){
        float2 p = shflx(a[i], m);
        a[i] = cadd(cmul(cs, a[i]), cmul(cx, p));
    }
}
__device__ __forceinline__ void pair_LL01(float2* a,
        float2 pA, float2 pB, float2 qC, float2 qD){
    float2 a0=a[0], a1=a[1], a2=a[2], a3=a[3];
    a[0] = cadd(cmul(pA,a0), cmul(pB,a3));
    a[3] = cadd(cmul(pB,a0), cmul(pA,a3));
    a[1] = cadd(cmul(qC,a1), cmul(qD,a2));
    a[2] = cadd(cmul(qD,a1), cmul(qC,a2));
}
__device__ __forceinline__ void pair_NN(float2* a, int lane, int LA, int LB,
        float2 pA, float2 pB, float2 qC, float2 qD){
    int M = (1<<LA) | (1<<LB);
    bool eq = ((((lane >> LA) ^ (lane >> LB)) & 1) == 0);
    float2 X = eq ? pA : qC;
    float2 Y = eq ? pB : qD;
    #pragma unroll
    for (int i = 0; i < 4; i++){
        float2 p = shflx(a[i], M);
        a[i] = cadd(cmul(X, a[i]), cmul(Y, p));
    }
}
__device__ __forceinline__ void pair_ML(float2* a, int lane, int LB,
        float2 pA, float2 pB, float2 qC, float2 qD){
    int lm = 1 << LB;
    int b4 = (lane >> LB) & 1;
    float2 Xi = b4 ? qC : pA, Yi = b4 ? qD : pB;
    float2 Xj = b4 ? pA : qC, Yj = b4 ? pB : qD;
    #pragma unroll
    for (int i = 0; i < 2; i++){
        int j = i | 2;
        float2 pj = shflx(a[j], lm);
        float2 pi = shflx(a[i], lm);
        a[i] = cadd(cmul(Xi, a[i]), cmul(Yi, pj));
        a[j] = cadd(cmul(Xj, a[j]), cmul(Yj, pi));
    }
}

// ---------------- setup builders (verified rounds 1-8) ---------------------------
__device__ void build_ufinal4(const float* vw, float2* F){
    float s1, c1, s2, c2, sz, cz;
    __sincosf(0.5f*vw[0], &s1, &c1);
    __sincosf(0.5f*vw[1], &s2, &c2);
    __sincosf(0.5f*vw[2], &sz, &cz);
    float2 m00 = make_float2( c1*c2,  s1*s2);
    float2 m01 = make_float2(-c1*s2, -c2*s1);
    float2 m10 = make_float2( c1*s2, -c2*s1);
    float2 m11 = make_float2( c1*c2, -s1*s2);
    float2 e0 = make_float2(cz, -sz);
    float2 e1 = make_float2(cz,  sz);
    F[0] = cmul(e0, m00); F[1] = cmul(e0, m01);
    F[2] = cmul(e1, m10); F[3] = cmul(e1, m11);
}
__device__ void lcompose_rx(float2* F, float c, float s){
    float2 is = make_float2(0.f, -s);
    float2 n0 = cadd(make_float2(c*F[0].x, c*F[0].y), cmul(is, F[2]));
    float2 n1 = cadd(make_float2(c*F[1].x, c*F[1].y), cmul(is, F[3]));
    float2 n2 = cadd(cmul(is, F[0]), make_float2(c*F[2].x, c*F[2].y));
    float2 n3 = cadd(cmul(is, F[1]), make_float2(c*F[3].x, c*F[3].y));
    F[0]=n0; F[1]=n1; F[2]=n2; F[3]=n3;
}
__device__ void lcompose_ry(float2* F, float c, float s){
    float2 n0 = make_float2(fmaf(c,F[0].x,-s*F[2].x), fmaf(c,F[0].y,-s*F[2].y));
    float2 n1 = make_float2(fmaf(c,F[1].x,-s*F[3].x), fmaf(c,F[1].y,-s*F[3].y));
    float2 n2 = make_float2(fmaf(s,F[0].x, c*F[2].x), fmaf(s,F[0].y, c*F[2].y));
    float2 n3 = make_float2(fmaf(s,F[1].x, c*F[3].x), fmaf(s,F[1].y, c*F[3].y));
    F[0]=n0; F[1]=n1; F[2]=n2; F[3]=n3;
}
__device__ void paircoef(const float* w, int layer, int pidx, float2* co){
    const float* wl = w + layer*48 + 3*pidx;
    float ca, sa, cb, sb, cg, sg;
    __sincosf(0.5f*wl[0], &sa, &ca);
    __sincosf(0.5f*wl[1], &sb, &cb);
    __sincosf(0.5f*wl[2], &sg, &cg);
    float A  = ca*cb + sa*sb;
    float Bi = ca*sb - cb*sa;
    float C  = ca*cb - sa*sb;
    float Di = -(sa*cb + ca*sb);
    float2 p  = make_float2(cg, -sg);
    float2 qf = make_float2(cg,  sg);
    co[0] = make_float2(p.x*A, p.y*A);
    co[1] = cmul(p,  make_float2(0.f, Bi));
    co[2] = make_float2(qf.x*C, qf.y*C);
    co[3] = cmul(qf, make_float2(0.f, Di));
}

__global__ void __launch_bounds__(CTA_THREADS, 1)
qpie_tree(const float* __restrict__ x,
          const float* __restrict__ w,
          const float* __restrict__ pw,
          float* __restrict__ out)
{
    const float c8 = 0.9238795325112867f;
    const float s8 = 0.3826834323650898f;

    __shared__ float2 sT[16];         // L0 record per-qubit e^{i pw/2}
    __shared__ float2 sXcs[8];        // (cos,sin) x_q/2
    __shared__ float2 sOL[64];        // L1 record lane tables (q2..q6)
    __shared__ float2 sOLoc[8];       // L1 record local tables (q0,q1)
    __shared__ float2 sOq7[2];        // L1 record q7 factors
    __shared__ float2 sPair[84];      // 21 pairs x 4
    __shared__ float2 sF01[32];       // Rx(x)*U0
    __shared__ float2 sF12p[32];      // Ry(x)*U1 (no D — deferred to stage C)
    __shared__ float2 sF2[32];        // U2
    __shared__ float2 sEL[32], sFL[32];   // L2 record lane tables (phi4±phi5)
    __shared__ float2 sELoc[4], sFLoc[4]; // L2 record local tables
    __shared__ float2 sEq7, sFq7;         // L2 record q7 factors
    __shared__ float2 sSA[256];       // stage A output state
    __shared__ float2 sSB[512];       // stage B output states (2)
    __shared__ float2 sExch[4096];    // per-pair exchange, double buffered
    __shared__ float  sRed[128];
    __shared__ int    sLast;

    int tid  = threadIdx.x;
    int lane = tid & 31;
    int wid  = tid >> 5;
    int sub  = wid & 1;               // q7 value of this warp
    int pairIdx = wid >> 1;           // 0..7
    int cta  = blockIdx.x;
    int b    = cta >> 3;              // batch
    int g    = cta & 7;               // branch bits 0..2
    const float* xb = x + b*8;

    int b3 = pairIdx & 1;
    int v4 = (pairIdx >> 1) & 1;
    int v5 = (pairIdx >> 2) & 1;

    // ================= cooperative setup (180 jobs, one round) =============
    {
        int job = tid;
        if (job < 16){
            int r = job >> 3, q = job & 7;
            float s, c; __sincosf(0.5f*pw[r*8 + q], &s, &c);
            sT[r*8 + q] = make_float2(c, s);
        } else if (job < 24){
            int q = job - 16;
            float s, c; __sincosf(0.5f*xb[q], &s, &c);
            sXcs[q] = make_float2(c, s);
        } else if (job < 88){        // L1 record lane tables (q2..q6)
            int k = job - 24; int r = k >> 5; int ln = k & 31;
            const float* pwa = pw + (2 + r)*8;
            float sum = 0.f;
            #pragma unroll
            for (int j = 0; j < 5; j++)
                if ((ln >> j) & 1) sum += pwa[2+j];
            float sp, cp; __sincosf(0.5f*sum, &sp, &cp);
            sOL[k] = make_float2(cp, sp);
        } else if (job < 96){        // L1 record local tables (q0,q1)
            int k = job - 88; int r = k >> 2; int i = k & 3;
            const float* pwa = pw + (2 + r)*8;
            float sum = 0.f;
            if (i & 1) sum += pwa[0];
            if (i & 2) sum += pwa[1];
            float sp, cp; __sincosf(0.5f*sum, &sp, &cp);
            sOLoc[k] = make_float2(cp, sp);
        } else if (job < 98){
            int r = job - 96;
            float sp, cp; __sincosf(0.5f*pw[(2 + r)*8 + 7], &sp, &cp);
            sOq7[r] = make_float2(cp, sp);
        } else if (job < 119){       // pair coefficients
            int k = job - 98; int layer = k/7, p = k - layer*7;
            paircoef(w, layer, p, sPair + k*4);
        } else if (job < 127){       // F01
            int q = job - 119;
            float2 F[4];
            build_ufinal4(w + 24 + 3*q, F);
            float s, c; __sincosf(0.5f*xb[q], &s, &c);
            lcompose_rx(F, c, s);
            sF01[q*4+0]=F[0]; sF01[q*4+1]=F[1]; sF01[q*4+2]=F[2]; sF01[q*4+3]=F[3];
        } else if (job < 135){       // F2
            int q = job - 127;
            float2 F[4];
            build_ufinal4(w + 96 + 24 + 3*q, F);
            sF2[q*4+0]=F[0]; sF2[q*4+1]=F[1]; sF2[q*4+2]=F[2]; sF2[q*4+3]=F[3];
        } else if (job < 143){       // F12' = Ry(x)*U1
            int q = job - 135;
            float2 F[4];
            build_ufinal4(w + 48 + 24 + 3*q, F);
            float s, c; __sincosf(0.5f*xb[q], &s, &c);
            lcompose_ry(F, c, s);
            sF12p[q*4+0]=F[0]; sF12p[q*4+1]=F[1]; sF12p[q*4+2]=F[2]; sF12p[q*4+3]=F[3];
        } else if (job < 175){       // L2 record lane tables
            int ln = job - 143;
            const float* p4 = pw + 32;
            const float* p5 = pw + 40;
            float A = 0.f, B = 0.f;
            #pragma unroll
            for (int j = 0; j < 5; j++)
                if ((ln >> j) & 1){ A += p4[2+j]; B += p5[2+j]; }
            A *= 0.5f; B *= 0.5f;
            float sp, cp;
            __sincosf(A + B, &sp, &cp); sEL[ln] = make_float2(cp, sp);
            __sincosf(A - B, &sp, &cp); sFL[ln] = make_float2(cp, sp);
        } else if (job < 179){       // L2 record local tables
            int i = job - 175;
            const float* p4 = pw + 32;
            const float* p5 = pw + 40;
            float A = 0.f, B = 0.f;
            if (i & 1){ A += p4[0]; B += p5[0]; }
            if (i & 2){ A += p4[1]; B += p5[1]; }
            A *= 0.5f; B *= 0.5f;
            float sp, cp;
            __sincosf(A + B, &sp, &cp); sELoc[i] = make_float2(cp, sp);
            __sincosf(A - B, &sp, &cp); sFLoc[i] = make_float2(cp, sp);
        } else if (job < 180){
            float A = 0.5f*pw[32+7], B = 0.5f*pw[40+7];
            float sp, cp;
            __sincosf(A + B, &sp, &cp); sEq7 = make_float2(cp, sp);
            __sincosf(A - B, &sp, &cp); sFq7 = make_float2(cp, sp);
        }
    }
    __syncthreads();

    float2 a[4];
    int t64 = sub*32 + lane;
    int myBase  = (pairIdx*64 + t64)*4;
    int pBaseSq = (pairIdx*64 + ((sub^1)*32 + lane))*4;
    int pBaseMP = (pairIdx*64 + ((sub^1)*32 + (lane^16)))*4;
    int barId = 1 + pairIdx;

    // ======================= STAGE A: layer 0 (pair 0 only) ================
    if (pairIdx == 0){
        // product-state init: H + Ry(x) + L0 record diagonals (bits b0,b1=g&3)
        {
            float sg0 = (g & 1) ? 1.f : -1.f;
            float sg1 = (g & 2) ? 1.f : -1.f;
            float2 g0[8], g1[8];
            #pragma unroll
            for (int q = 0; q < 8; q++){
                float2 t0 = sT[q], t1 = sT[8+q];
                float2 E = cmul(make_float2(t0.x, sg0*t0.y),
                                make_float2(t1.x, sg1*t1.y));
                float2 cs = sXcs[q];
                float gm = cs.x - cs.y, gp = cs.x + cs.y;
                g0[q] = make_float2(gm, 0.f);
                g1[q] = make_float2(gp*E.x, gp*E.y);
            }
            float2 lp = make_float2(0.015625f, 0.f);
            #pragma unroll
            for (int j = 0; j < 5; j++)
                lp = cmul(lp, ((lane >> j) & 1) ? g1[2+j] : g0[2+j]);
            lp = cmul(lp, sub ? g1[7] : g0[7]);
            a[0] = cmul(lp, cmul(g0[0], g0[1]));
            a[1] = cmul(lp, cmul(g1[0], g0[1]));
            a[2] = cmul(lp, cmul(g0[0], g1[1]));
            a[3] = cmul(lp, cmul(g1[0], g1[1]));
        }
        const float2* P = sPair;
        pair_LL01(a, P[0], P[1], P[2], P[3]);
        if (g & 1){
            float2 ai = a[1], aj = a[3];
            a[1] = make_float2(fmaf(c8, ai.x,  s8*aj.y), fmaf(c8, ai.y, -s8*aj.x));
            a[3] = make_float2(fmaf(c8, aj.x,  s8*ai.y), fmaf(c8, aj.y, -s8*ai.x));
        }
        pair_NN(a, lane, 0, 1, P[4], P[5], P[6], P[7]);
        if (g & 2){
            bool act = lane & 1;
            #pragma unroll
            for (int i = 0; i < 4; i++){
                float2 p = shflx(a[i], 2);
                if (act)
                    a[i] = make_float2(fmaf(c8, a[i].x,  s8*p.y), fmaf(c8, a[i].y, -s8*p.x));
            }
        }
        pair_NN(a, lane, 2, 3, P[8], P[9], P[10], P[11]);
        {   // (q6,q7) exchange
            bool eq = (((lane >> 4) & 1) == sub);
            float2 X = eq ? P[12] : P[14];
            float2 Y = eq ? P[13] : P[15];
            float2* mb = sExch + myBase;
            mb[0]=a[0]; mb[1]=a[1]; mb[2]=a[2]; mb[3]=a[3];
            barpair(barId);
            const float2* pb = sExch + pBaseMP;
            #pragma unroll
            for (int i = 0; i < 4; i++)
                a[i] = cadd(cmul(X, a[i]), cmul(Y, pb[i]));
        }
        pair_ML(a, lane, 0,    P[16], P[17], P[18], P[19]);
        pair_NN(a, lane, 1, 2, P[20], P[21], P[22], P[23]);
        pair_NN(a, lane, 3, 4, P[24], P[25], P[26], P[27]);
        // F01 gates
        #pragma unroll
        for (int q = 0; q < 7; q++){
            const float2* F = sF01 + q*4;
            if (q < 2) sq_local(a, q, F[0], F[1], F[2], F[3]);
            else       sq_lane (a, lane, q-2, F[0], F[1], F[2], F[3]);
        }
        {   // q7 via exchange (second buffer)
            const float2* F = sF01 + 28;
            float2 us = sub ? F[3] : F[0];
            float2 ux = sub ? F[2] : F[1];
            float2* mb = sExch + 2048 + myBase;
            mb[0]=a[0]; mb[1]=a[1]; mb[2]=a[2]; mb[3]=a[3];
            barpair(barId);
            const float2* pb = sExch + 2048 + pBaseSq;
            #pragma unroll
            for (int i = 0; i < 4; i++)
                a[i] = cadd(cmul(us, a[i]), cmul(ux, pb[i]));
        }
        // publish stage-A state
        float2* dst = sSA + t64*4;
        dst[0]=a[0]; dst[1]=a[1]; dst[2]=a[2]; dst[3]=a[3];
    }
    __syncthreads();

    // ======================= STAGE B: layer 1 (pairs 0,1) ==================
    if (pairIdx < 2){
        const float2* src = sSA + t64*4;
        a[0]=src[0]; a[1]=src[1]; a[2]=src[2]; a[3]=src[3];
        // merged L1 record diagonal: v2 = g>>2, v3 = pairIdx
        {
            int v2 = (g >> 2) & 1, v3 = b3;
            float2 eL2 = cmul(sOL[lane],      sub ? sOq7[0] : make_float2(1.f,0.f));
            float2 eL3 = cmul(sOL[32 + lane], sub ? sOq7[1] : make_float2(1.f,0.f));
            int par = v2 ^ v3;
            float sgn = v2 ? -1.f : 1.f;
            #pragma unroll
            for (int i = 0; i < 4; i++){
                float2 e2 = cmul(eL2, sOLoc[i]);
                float2 e3 = cmul(eL3, sOLoc[4+i]);
                float m = (v2 ? e2.y : e2.x) * (v3 ? e3.y : e3.x);
                if (par) a[i] = make_float2(a[i].y*m, -a[i].x*m);
                else { float mm = sgn*m; a[i] = make_float2(a[i].x*mm, a[i].y*mm); }
            }
        }
        const float2* P = sPair + 28;
        pair_LL01(a, P[0], P[1], P[2], P[3]);
        if ((g >> 2) & 1){
            float2 ai = a[1], aj = a[3];
            a[1] = make_float2(fmaf(c8, ai.x,  s8*aj.y), fmaf(c8, ai.y, -s8*aj.x));
            a[3] = make_float2(fmaf(c8, aj.x,  s8*ai.y), fmaf(c8, aj.y, -s8*ai.x));
        }
        pair_NN(a, lane, 0, 1, P[4], P[5], P[6], P[7]);
        if (b3){
            bool act = lane & 1;
            #pragma unroll
            for (int i = 0; i < 4; i++){
                float2 p = shflx(a[i], 2);
                if (act)
                    a[i] = make_float2(fmaf(c8, a[i].x,  s8*p.y), fmaf(c8, a[i].y, -s8*p.x));
            }
        }
        pair_NN(a, lane, 2, 3, P[8], P[9], P[10], P[11]);
        {
            bool eq = (((lane >> 4) & 1) == sub);
            float2 X = eq ? P[12] : P[14];
            float2 Y = eq ? P[13] : P[15];
            float2* mb = sExch + myBase;
            mb[0]=a[0]; mb[1]=a[1]; mb[2]=a[2]; mb[3]=a[3];
            barpair(barId);
            const float2* pb = sExch + pBaseMP;
            #pragma unroll
            for (int i = 0; i < 4; i++)
                a[i] = cadd(cmul(X, a[i]), cmul(Y, pb[i]));
        }
        pair_ML(a, lane, 0,    P[16], P[17], P[18], P[19]);
        pair_NN(a, lane, 1, 2, P[20], P[21], P[22], P[23]);
        pair_NN(a, lane, 3, 4, P[24], P[25], P[26], P[27]);
        #pragma unroll
        for (int q = 0; q < 7; q++){
            const float2* F = sF12p + q*4;
            if (q < 2) sq_local(a, q, F[0], F[1], F[2], F[3]);
            else       sq_lane (a, lane, q-2, F[0], F[1], F[2], F[3]);
        }
        {
            const float2* F = sF12p + 28;
            float2 us = sub ? F[3] : F[0];
            float2 ux = sub ? F[2] : F[1];
            float2* mb = sExch + 2048 + myBase;
            mb[0]=a[0]; mb[1]=a[1]; mb[2]=a[2]; mb[3]=a[3];
            barpair(barId);
            const float2* pb = sExch + 2048 + pBaseSq;
            #pragma unroll
            for (int i = 0; i < 4; i++)
                a[i] = cadd(cmul(us, a[i]), cmul(ux, pb[i]));
        }
        float2* dst = sSB + (b3*64 + t64)*4;
        dst[0]=a[0]; dst[1]=a[1]; dst[2]=a[2]; dst[3]=a[3];
    }
    __syncthreads();

    // ======================= STAGE C: layer 2 (all 8 pairs) ================
    {
        const float2* src = sSB + (b3*64 + t64)*4;
        a[0]=src[0]; a[1]=src[1]; a[2]=src[2]; a[3]=src[3];
        // L2 record diagonal D(v4,v5)
        {
            bool same = !(v4 ^ v5);
            float cs = v4 ? 1.f : -1.f;
            float2 tL = same ? sEL[lane] : sFL[lane];
            if (sub) tL = cmul(tL, same ? sEq7 : sFq7);
            #pragma unroll
            for (int i = 0; i < 4; i++){
                float2 f = cmul(tL, same ? sELoc[i] : sFLoc[i]);
                f.y *= cs;
                a[i] = cmul(a[i], f);
            }
        }
        const float2* P = sPair + 56;
        pair_LL01(a, P[0], P[1], P[2], P[3]);
        if (v4){
            float2 ai = a[1], aj = a[3];
            a[1] = make_float2(fmaf(c8, ai.x,  s8*aj.y), fmaf(c8, ai.y, -s8*aj.x));
            a[3] = make_float2(fmaf(c8, aj.x,  s8*ai.y), fmaf(c8, aj.y, -s8*ai.x));
        }
        pair_NN(a, lane, 0, 1, P[4], P[5], P[6], P[7]);
        if (v5){
            bool act = lane & 1;
            #pragma unroll
            for (int i = 0; i < 4; i++){
                float2 p = shflx(a[i], 2);
                if (act)
                    a[i] = make_float2(fmaf(c8, a[i].x,  s8*p.y), fmaf(c8, a[i].y, -s8*p.x));
            }
        }
        pair_NN(a, lane, 2, 3, P[8], P[9], P[10], P[11]);
        {
            bool eq = (((lane >> 4) & 1) == sub);
            float2 X = eq ? P[12] : P[14];
            float2 Y = eq ? P[13] : P[15];
            float2* mb = sExch + myBase;
            mb[0]=a[0]; mb[1]=a[1]; mb[2]=a[2]; mb[3]=a[3];
            barpair(barId);
            const float2* pb = sExch + pBaseMP;
            #pragma unroll
            for (int i = 0; i < 4; i++)
                a[i] = cadd(cmul(X, a[i]), cmul(Y, pb[i]));
        }
        pair_ML(a, lane, 0,    P[16], P[17], P[18], P[19]);
        pair_NN(a, lane, 1, 2, P[20], P[21], P[22], P[23]);
        pair_NN(a, lane, 3, 4, P[24], P[25], P[26], P[27]);
        #pragma unroll
        for (int q = 0; q < 7; q++){
            const float2* F = sF2 + q*4;
            if (q < 2) sq_local(a, q, F[0], F[1], F[2], F[3]);
            else       sq_lane (a, lane, q-2, F[0], F[1], F[2], F[3]);
        }
        {
            const float2* F = sF2 + 28;
            float2 us = sub ? F[3] : F[0];
            float2 ux = sub ? F[2] : F[1];
            float2* mb = sExch + 2048 + myBase;
            mb[0]=a[0]; mb[1]=a[1]; mb[2]=a[2]; mb[3]=a[3];
            barpair(barId);
            const float2* pb = sExch + 2048 + pBaseSq;
            #pragma unroll
            for (int i = 0; i < 4; i++)
                a[i] = cadd(cmul(us, a[i]), cmul(ux, pb[i]));
        }
    }

    // ================= measurement & fused reduction =======================
    float e[8];
    float tot = 0.f;
    e[0] = 0.f; e[1] = 0.f;
    #pragma unroll
    for (int i = 0; i < 4; i++){
        float p = fmaf(a[i].x, a[i].x, a[i].y*a[i].y);
        tot += p;
        e[0] += (i & 1) ? -p : p;
        e[1] += (i & 2) ? -p : p;
    }
    #pragma unroll
    for (int q = 0; q < 5; q++)
        e[2+q] = ((lane >> q) & 1) ? -tot : tot;
    e[7] = sub ? -tot : tot;

    #pragma unroll
    for (int q = 0; q < 8; q++){
        #pragma unroll
        for (int s = 16; s; s >>= 1)
            e[q] += __shfl_xor_sync(0xffffffffu, e[q], s);
    }
    if (lane == 0){
        #pragma unroll
        for (int q = 0; q < 8; q++) sRed[wid*8 + q] = e[q];
    }
    __syncthreads();

    if (tid < 8){
        float s = 0.f;
        #pragma unroll
        for (int wq = 0; wq < 16; wq++) s += sRed[wq*8 + tid];
        g_part[cta*8 + tid] = s;
        __threadfence();
    }
    __syncthreads();

    if (tid == 0){
        __threadfence();
        unsigned int t = atomicAdd(&g_ticket, 1u);
        sLast = (t == NCTA - 1) ? 1 : 0;
    }
    __syncthreads();

    if (sLast){
        __threadfence();
        if (tid < 128){
            int bb = tid >> 3, q = tid & 7;
            float s = 0.f;
            #pragma unroll
            for (int k = 0; k < 8; k++)
                s += g_part[(bb*8 + k)*8 + q];
            out[tid] = s;
        }
        __syncthreads();
        if (tid == 0) g_ticket = 0;
    }
}

extern "C" void kernel_launch(void* const* d_in, const int* in_sizes, int n_in,
                              void* d_out, int out_size){
    const float* x  = (const float*)d_in[0];   // (16, 8)
    const float* w  = (const float*)d_in[1];   // (3, 48)
    const float* pw = (const float*)d_in[2];   // (3, 2, 8)
    float* out = (float*)d_out;                // (16, 8)

    qpie_tree<<<NCTA, CTA_THREADS>>>(x, w, pw, out);
}